// round 15
// baseline (speedup 1.0000x reference)
#include <cuda_runtime.h>
#include <cstdint>
#include <math_constants.h>

#define BB   32
#define LQ   512
#define LK   2048
#define DD   768
#define D4   (DD/4)     // 192
#define NQC  16
#define QPC  (LQ/NQC)   // 32
#define RPW  32         // rows (keys) per warp
#define WPB  8          // warps per block
#define RPB  (RPW*WPB)  // 256 rows per block
#define NCH  (LK/RPB)   // 8 chunks per batch
#define TPB  256
#define ESPL 16
#define EPB  (DD/ESPL)  // 48

typedef unsigned long long u64;

// packed f32x2 helpers (SASS FFMA2/FMUL2 — only reachable via explicit PTX)
__device__ __forceinline__ u64 pack2(float x, float y) {
    u64 r; asm("mov.b64 %0, {%1, %2};" : "=l"(r) : "f"(x), "f"(y)); return r;
}
__device__ __forceinline__ u64 fma2(u64 a, u64 b, u64 c) {
    u64 d; asm("fma.rn.f32x2 %0, %1, %2, %3;" : "=l"(d) : "l"(a), "l"(b), "l"(c)); return d;
}
__device__ __forceinline__ u64 mul2(u64 a, u64 b) {
    u64 d; asm("mul.rn.f32x2 %0, %1, %2;" : "=l"(d) : "l"(a), "l"(b)); return d;
}
__device__ __forceinline__ float hadd2(u64 v) {
    float x, y; asm("mov.b64 {%0, %1}, %2;" : "=f"(x), "=f"(y) : "l"(v)); return x + y;
}

union F4U { float4 f; u64 u[2]; };

// scratch (device globals — no allocation allowed)
__device__ float g_sp  [BB*NQC*DD];
__device__ float g_ssum[BB*DD];
__device__ float g_wp  [ESPL*BB*DD];
__device__ float g_pm  [BB*NCH];
__device__ float g_pl  [BB*NCH];
__device__ float g_pacc[BB*NCH*DD];
__device__ float g_vin [BB*DD];
__device__ int   g_cnt_s[BB];   // zero-init; self-resets each use
__device__ int   g_cnt_a[BB];   // zero-init; self-resets each use

// ---------------- K1: row-sums of sentence_rep, fused partial+reduce (R14, verified) ----
// grid (NQC, BB), 192 threads, float4 lanes. Last block per b reduces (fixed order).
__global__ void k_ssum(const float* __restrict__ sr) {
    int qc = blockIdx.x, b = blockIdx.y, t = threadIdx.x;   // t < 192
    const float4* p = reinterpret_cast<const float4*>(sr) +
                      ((size_t)b*LQ + (size_t)qc*QPC)*D4 + t;
    float4 a = make_float4(0.f,0.f,0.f,0.f);
#pragma unroll
    for (int q = 0; q < QPC; q++) {
        float4 v = p[(size_t)q*D4];
        a.x += v.x; a.y += v.y; a.z += v.z; a.w += v.w;
    }
    reinterpret_cast<float4*>(g_sp)[(b*NQC + qc)*D4 + t] = a;

    __threadfence();
    __syncthreads();
    __shared__ int s_last;
    if (t == 0) s_last = (atomicAdd(&g_cnt_s[b], 1) == NQC-1);
    __syncthreads();
    if (s_last) {
        if (t == 0) g_cnt_s[b] = 0;   // reset for next graph replay
        __threadfence();
        float4 r = make_float4(0.f,0.f,0.f,0.f);
#pragma unroll
        for (int c = 0; c < NQC; c++) {
            float4 v = reinterpret_cast<const float4*>(g_sp)[(b*NQC + c)*D4 + t];
            r.x += v.x; r.y += v.y; r.z += v.z; r.w += v.w;
        }
        reinterpret_cast<float4*>(g_ssum)[b*D4 + t] = r;
    }
}

// ---------------- K2: fused qsum+w — per-block qsum slice, then Wk phase ----------------
// grid (BB/2, ESPL) = 256 blocks, 192 threads (6 warps).
// Block (b-pair, z): qs[2][EPB] = ssum[b0..b0+1] · Wq[e0..e0+EPB-1,:] + 512*bq,
// then g_wp[z,b,d] = sum_{e in slice} qs * Wk[e,d] with float4 d-lanes.
__global__ void k_wq(const float* __restrict__ Wq, const float* __restrict__ bq,
                     const float* __restrict__ Wk) {
    int b0 = blockIdx.x * 2;
    int z  = blockIdx.y;
    int e0 = z * EPB;
    int t = threadIdx.x, warp = t >> 5, lane = t & 31;   // 6 warps

    __shared__ float s_ssum[2*DD];
    __shared__ float s_qs[2*EPB];    // [bsel*EPB + je]

    // load ssum rows for both b's (float4)
#pragma unroll
    for (int i = t; i < 2*D4; i += 192)
        reinterpret_cast<float4*>(s_ssum)[i] =
            reinterpret_cast<const float4*>(g_ssum)[(size_t)b0*D4 + i];
    __syncthreads();

    // phase 1: 96 dots of length 768, 16 per warp, 8-interleaved
    const float4* Wq4 = reinterpret_cast<const float4*>(Wq);
    const float4* ss4 = reinterpret_cast<const float4*>(s_ssum);
#pragma unroll
    for (int g = 0; g < 16; g += 8) {
        float acc[8];
#pragma unroll
        for (int j = 0; j < 8; j++) acc[j] = 0.f;
#pragma unroll
        for (int i = 0; i < 6; i++) {
#pragma unroll
            for (int j = 0; j < 8; j++) {
                int dj = warp*16 + g + j;          // 0..95
                int bsel = dj / EPB, je = dj % EPB;
                float4 wv = Wq4[(size_t)(e0 + je)*D4 + lane + 32*i];
                float4 sv = ss4[bsel*D4 + lane + 32*i];
                acc[j] = fmaf(wv.x, sv.x, acc[j]);
                acc[j] = fmaf(wv.y, sv.y, acc[j]);
                acc[j] = fmaf(wv.z, sv.z, acc[j]);
                acc[j] = fmaf(wv.w, sv.w, acc[j]);
            }
        }
#pragma unroll
        for (int o = 16; o; o >>= 1) {
#pragma unroll
            for (int j = 0; j < 8; j++)
                acc[j] += __shfl_xor_sync(0xffffffffu, acc[j], o);
        }
        if (lane == 0) {
#pragma unroll
            for (int j = 0; j < 8; j++) {
                int dj = warp*16 + g + j;
                int je = dj % EPB;
                s_qs[dj] = acc[j] + 512.0f * bq[e0 + je];
            }
        }
    }
    __syncthreads();

    // phase 2: thread owns 4 consecutive d (float4 of Wk row), 48 LDG.128
    const float4* Wk4 = reinterpret_cast<const float4*>(Wk);
    float4 a0 = make_float4(0.f,0.f,0.f,0.f);
    float4 a1 = make_float4(0.f,0.f,0.f,0.f);
#pragma unroll
    for (int e = 0; e < EPB; e++) {
        float4 wk = Wk4[(size_t)(e0 + e)*D4 + t];
        float q0 = s_qs[e], q1 = s_qs[EPB + e];
        a0.x = fmaf(wk.x, q0, a0.x); a0.y = fmaf(wk.y, q0, a0.y);
        a0.z = fmaf(wk.z, q0, a0.z); a0.w = fmaf(wk.w, q0, a0.w);
        a1.x = fmaf(wk.x, q1, a1.x); a1.y = fmaf(wk.y, q1, a1.y);
        a1.z = fmaf(wk.z, q1, a1.z); a1.w = fmaf(wk.w, q1, a1.w);
    }
    reinterpret_cast<float4*>(g_wp)[(size_t)(z*BB + b0+0)*D4 + t] = a0;
    reinterpret_cast<float4*>(g_wp)[(size_t)(z*BB + b0+1)*D4 + t] = a1;
}

// ---------------- K3: warp-autonomous k_attn (R14 mainloop) + fused combine ----------
// grid = (NCH, BB) = 256 blocks, 256 threads.
__global__ void __launch_bounds__(TPB) k_attn(const float* __restrict__ cr) {
    int b = blockIdx.y, ch = blockIdx.x;
    int tid = threadIdx.x, warp = tid >> 5, lane = tid & 31;

    __shared__ float s_ws[DD];
    __shared__ float s_acc[WPB][DD];
    __shared__ float s_m[WPB], s_l[WPB];
    __shared__ float s_f[WPB];
    __shared__ float s_cf[NCH];
    __shared__ float s_invL;

    // ws = sum of e-split partials (L2-resident)
    for (int i = tid; i < DD; i += TPB) {
        float a = 0.f;
#pragma unroll
        for (int z = 0; z < ESPL; z++) a += g_wp[(z*BB + b)*DD + i];
        s_ws[i] = a;
    }
    __syncthreads();

    // w into packed registers: 12 u64 pairs covering float4 slots lane+32*i
    u64 w[12];
    const float4* ws4 = reinterpret_cast<const float4*>(s_ws);
#pragma unroll
    for (int i = 0; i < 6; i++) {
        F4U t; t.f = ws4[lane + 32*i];
        w[2*i]   = t.u[0];
        w[2*i+1] = t.u[1];
    }

    const float4* rbase = reinterpret_cast<const float4*>(cr) +
                          ((size_t)b*LK + (size_t)ch*RPB + (size_t)warp*RPW)*D4 + lane;

    float m = -CUDART_INF_F, l = 0.f;
    u64 acc[12];
#pragma unroll
    for (int j = 0; j < 12; j++) acc[j] = 0ull;   // (0.0f, 0.0f)

    for (int r = 0; r < RPW; r += 2) {
        F4U v0[6], v1[6];
        const float4* row0 = rbase + (size_t)r*D4;
        const float4* row1 = row0 + D4;
#pragma unroll
        for (int i = 0; i < 6; i++) v0[i].f = row0[32*i];
#pragma unroll
        for (int i = 0; i < 6; i++) v1[i].f = row1[32*i];

        // packed dot products (24 FFMA2 instead of 48 FFMA)
        u64 s0p = 0ull, s1p = 0ull;
#pragma unroll
        for (int i = 0; i < 6; i++) {
            s0p = fma2(v0[i].u[0], w[2*i],   s0p);
            s0p = fma2(v0[i].u[1], w[2*i+1], s0p);
            s1p = fma2(v1[i].u[0], w[2*i],   s1p);
            s1p = fma2(v1[i].u[1], w[2*i+1], s1p);
        }
        float s0 = hadd2(s0p);
        float s1 = hadd2(s1p);
#pragma unroll
        for (int o = 16; o; o >>= 1) {
            s0 += __shfl_xor_sync(0xffffffffu, s0, o);
            s1 += __shfl_xor_sync(0xffffffffu, s1, o);
        }

        float mnew = fmaxf(m, fmaxf(s0, s1));
        float p0 = __expf(s0 - mnew);
        float p1 = __expf(s1 - mnew);
        if (mnew != m) {                       // warp-uniform branch
            float scale = __expf(m - mnew);    // 0 on first pair (m=-inf)
            l *= scale;
            u64 sc2 = pack2(scale, scale);
#pragma unroll
            for (int j = 0; j < 12; j++) acc[j] = mul2(acc[j], sc2);
            m = mnew;
        }
        l += p0 + p1;

        u64 p0p = pack2(p0, p0);
        u64 p1p = pack2(p1, p1);
#pragma unroll
        for (int i = 0; i < 6; i++) {
            acc[2*i]   = fma2(p0p, v0[i].u[0], acc[2*i]);
            acc[2*i+1] = fma2(p0p, v0[i].u[1], acc[2*i+1]);
            acc[2*i]   = fma2(p1p, v1[i].u[0], acc[2*i]);
            acc[2*i+1] = fma2(p1p, v1[i].u[1], acc[2*i+1]);
        }
    }

    // per-warp results to smem (same float4-slot layout -> natural dim order)
    if (lane == 0) { s_m[warp] = m; s_l[warp] = l; }
    float4* sa = reinterpret_cast<float4*>(s_acc[warp]);
#pragma unroll
    for (int i = 0; i < 6; i++) {
        F4U t; t.u[0] = acc[2*i]; t.u[1] = acc[2*i+1];
        sa[lane + 32*i] = t.f;
    }
    __syncthreads();

    // block combine -> chunk partial
    if (tid == 0) {
        float M = -CUDART_INF_F;
#pragma unroll
        for (int ww = 0; ww < WPB; ww++) M = fmaxf(M, s_m[ww]);
        float L = 0.f;
#pragma unroll
        for (int ww = 0; ww < WPB; ww++) {
            float f = __expf(s_m[ww] - M);
            s_f[ww] = f;
            L += s_l[ww] * f;
        }
        int cidx = b*NCH + ch;
        g_pm[cidx] = M; g_pl[cidx] = L;
    }
    __syncthreads();
    if (tid < D4) {
        float4 a = make_float4(0.f,0.f,0.f,0.f);
#pragma unroll
        for (int ww = 0; ww < WPB; ww++) {
            float f = s_f[ww];
            float4 v = reinterpret_cast<const float4*>(s_acc[ww])[tid];
            a.x = fmaf(f, v.x, a.x); a.y = fmaf(f, v.y, a.y);
            a.z = fmaf(f, v.z, a.z); a.w = fmaf(f, v.w, a.w);
        }
        reinterpret_cast<float4*>(g_pacc)[(b*NCH + ch)*D4 + tid] = a;
    }

    // ---- fused cross-chunk combine: last block per b -> g_vin[b] ----
    __threadfence();
    __syncthreads();
    __shared__ int s_last;
    if (tid == 0) s_last = (atomicAdd(&g_cnt_a[b], 1) == NCH-1);
    __syncthreads();
    if (s_last) {
        if (tid == 0) {
            g_cnt_a[b] = 0;   // reset for next graph replay
            __threadfence();
            float M = -CUDART_INF_F;
#pragma unroll
            for (int c = 0; c < NCH; c++) M = fmaxf(M, g_pm[b*NCH + c]);
            float L = 0.f;
#pragma unroll
            for (int c = 0; c < NCH; c++) {
                float fc = __expf(g_pm[b*NCH + c] - M);
                s_cf[c] = fc;
                L += g_pl[b*NCH + c] * fc;
            }
            s_invL = 1.0f / L;
        }
        __syncthreads();
        if (tid < D4) {
            float invL = s_invL;
            float4 v = make_float4(0.f,0.f,0.f,0.f);
#pragma unroll
            for (int c = 0; c < NCH; c++) {
                float fc = s_cf[c];
                float4 a4 = reinterpret_cast<const float4*>(g_pacc)[(b*NCH + c)*D4 + tid];
                v.x = fmaf(a4.x, fc, v.x); v.y = fmaf(a4.y, fc, v.y);
                v.z = fmaf(a4.z, fc, v.z); v.w = fmaf(a4.w, fc, v.w);
            }
            v.x *= invL; v.y *= invL; v.z *= invL; v.w *= invL;
            reinterpret_cast<float4*>(g_vin)[b*D4 + tid] = v;
        }
    }
}

// ---------------- K4: out[b,e] = v_in[b,:]·Wv[e,:] + bv[e] ----------------
__global__ void k_out(const float* __restrict__ Wv, const float* __restrict__ bv,
                      float* __restrict__ out) {
    int e = blockIdx.x;
    __shared__ float wrow[DD];
    for (int i = threadIdx.x; i < D4; i += 128)
        reinterpret_cast<float4*>(wrow)[i] =
            reinterpret_cast<const float4*>(Wv + (size_t)e*DD)[i];
    __syncthreads();
    int warp = threadIdx.x >> 5, lane = threadIdx.x & 31;
    float bve = bv[e];
    const float4* w4 = reinterpret_cast<const float4*>(wrow);
    for (int b = warp; b < BB; b += 4) {
        const float4* v4 = reinterpret_cast<const float4*>(g_vin + b*DD);
        float acc = 0.f;
#pragma unroll
        for (int i = 0; i < D4/32; i++) {
            float4 w = w4[lane + 32*i], v = v4[lane + 32*i];
            acc = fmaf(w.x, v.x, acc); acc = fmaf(w.y, v.y, acc);
            acc = fmaf(w.z, v.z, acc); acc = fmaf(w.w, v.w, acc);
        }
#pragma unroll
        for (int o = 16; o; o >>= 1) acc += __shfl_xor_sync(0xffffffffu, acc, o);
        if (lane == 0) out[b*DD + e] = acc + bve;
    }
}

extern "C" void kernel_launch(void* const* d_in, const int* in_sizes, int n_in,
                              void* d_out, int out_size) {
    const float* sr = (const float*)d_in[0];   // sentence_rep [32,512,768]
    const float* cr = (const float*)d_in[1];   // comment_rep  [32,2048,768]
    const float* Wq = (const float*)d_in[2];
    const float* bq = (const float*)d_in[3];
    const float* Wk = (const float*)d_in[4];
    // d_in[5] = bk — exactly cancels in softmax, unused
    const float* Wv = (const float*)d_in[6];
    const float* bv = (const float*)d_in[7];
    float* out = (float*)d_out;

    k_ssum<<<dim3(NQC, BB), D4>>>(sr);
    k_wq<<<dim3(BB/2, ESPL), D4>>>(Wq, bq, Wk);
    k_attn<<<dim3(NCH, BB), TPB>>>(cr);
    k_out<<<DD, 128>>>(Wv, bv, out);
}

// round 16
// speedup vs baseline: 1.2183x; 1.2183x over previous
#include <cuda_runtime.h>
#include <cstdint>
#include <math_constants.h>

#define BB   32
#define LQ   512
#define LK   2048
#define DD   768
#define D4   (DD/4)     // 192
#define NQC  16
#define QPC  (LQ/NQC)   // 32
#define RPW  32         // rows (keys) per warp
#define WPB  8          // warps per block
#define RPB  (RPW*WPB)  // 256 rows per block
#define NCH  (LK/RPB)   // 8 chunks per batch
#define TPB  256
#define ESPL 16
#define EPB  (DD/ESPL)  // 48

typedef unsigned long long u64;

// packed f32x2 helpers (SASS FFMA2/FMUL2 — only reachable via explicit PTX)
__device__ __forceinline__ u64 pack2(float x, float y) {
    u64 r; asm("mov.b64 %0, {%1, %2};" : "=l"(r) : "f"(x), "f"(y)); return r;
}
__device__ __forceinline__ u64 fma2(u64 a, u64 b, u64 c) {
    u64 d; asm("fma.rn.f32x2 %0, %1, %2, %3;" : "=l"(d) : "l"(a), "l"(b), "l"(c)); return d;
}
__device__ __forceinline__ u64 mul2(u64 a, u64 b) {
    u64 d; asm("mul.rn.f32x2 %0, %1, %2;" : "=l"(d) : "l"(a), "l"(b)); return d;
}
__device__ __forceinline__ float hadd2(u64 v) {
    float x, y; asm("mov.b64 {%0, %1}, %2;" : "=f"(x), "=f"(y) : "l"(v)); return x + y;
}

union F4U { float4 f; u64 u[2]; };

// scratch (device globals — no allocation allowed)
__device__ float g_sp  [BB*NQC*DD];
__device__ float g_ssum[BB*DD];
__device__ float g_qsum[BB*DD];
__device__ float g_wp  [ESPL*BB*DD];
__device__ float g_pm  [BB*NCH];
__device__ float g_pl  [BB*NCH];
__device__ float g_pacc[BB*NCH*DD];
__device__ float g_vin [BB*DD];
__device__ int   g_cnt [BB];    // zero-init; self-resets each use

// ---------------- K1: row-sums of sentence_rep, fused partial+reduce (R14, verified) ----
__global__ void k_ssum(const float* __restrict__ sr) {
    int qc = blockIdx.x, b = blockIdx.y, t = threadIdx.x;   // t < 192
    const float4* p = reinterpret_cast<const float4*>(sr) +
                      ((size_t)b*LQ + (size_t)qc*QPC)*D4 + t;
    float4 a = make_float4(0.f,0.f,0.f,0.f);
#pragma unroll
    for (int q = 0; q < QPC; q++) {
        float4 v = p[(size_t)q*D4];
        a.x += v.x; a.y += v.y; a.z += v.z; a.w += v.w;
    }
    reinterpret_cast<float4*>(g_sp)[(b*NQC + qc)*D4 + t] = a;

    __threadfence();
    __syncthreads();
    __shared__ int s_last;
    if (t == 0) s_last = (atomicAdd(&g_cnt[b], 1) == NQC-1);
    __syncthreads();
    if (s_last) {
        if (t == 0) g_cnt[b] = 0;   // reset for next graph replay
        float4 r = make_float4(0.f,0.f,0.f,0.f);
#pragma unroll
        for (int c = 0; c < NQC; c++) {
            float4 v = reinterpret_cast<const float4*>(g_sp)[(b*NQC + c)*D4 + t];
            r.x += v.x; r.y += v.y; r.z += v.z; r.w += v.w;
        }
        reinterpret_cast<float4*>(g_ssum)[b*D4 + t] = r;
    }
}

// ---------------- K2: q_sum[b,e] — 8 interleaved dot products per warp (R9, verified) ----
__global__ void k_qsum(const float* __restrict__ Wq, const float* __restrict__ bq) {
    int e = blockIdx.x;
    __shared__ float wrow[DD];
    for (int i = threadIdx.x; i < D4; i += 128)
        reinterpret_cast<float4*>(wrow)[i] =
            reinterpret_cast<const float4*>(Wq + (size_t)e*DD)[i];
    __syncthreads();
    int warp = threadIdx.x >> 5, lane = threadIdx.x & 31;
    int b0 = warp * 8;

    float4 w[6];
    const float4* w4 = reinterpret_cast<const float4*>(wrow);
#pragma unroll
    for (int i = 0; i < 6; i++) w[i] = w4[lane + 32*i];

    const float4* s4 = reinterpret_cast<const float4*>(g_ssum);
    float acc[8];
#pragma unroll
    for (int j = 0; j < 8; j++) acc[j] = 0.f;

#pragma unroll
    for (int i = 0; i < 6; i++) {
#pragma unroll
        for (int j = 0; j < 8; j++) {
            float4 s = s4[(size_t)(b0 + j)*D4 + lane + 32*i];
            acc[j] = fmaf(w[i].x, s.x, acc[j]);
            acc[j] = fmaf(w[i].y, s.y, acc[j]);
            acc[j] = fmaf(w[i].z, s.z, acc[j]);
            acc[j] = fmaf(w[i].w, s.w, acc[j]);
        }
    }
#pragma unroll
    for (int o = 16; o; o >>= 1) {
#pragma unroll
        for (int j = 0; j < 8; j++)
            acc[j] += __shfl_xor_sync(0xffffffffu, acc[j], o);
    }
    if (lane == 0) {
        float be = 512.0f * bq[e];
#pragma unroll
        for (int j = 0; j < 8; j++)
            g_qsum[(b0 + j)*DD + e] = acc[j] + be;
    }
}

// ---------------- K3: w partials — R3 shape, full unroll (R14, verified) ----------------
__global__ void k_w(const float* __restrict__ Wk) {
    int d  = blockIdx.x * 128 + threadIdx.x;
    int b0 = blockIdx.y * 2;
    int e0 = blockIdx.z * EPB;
    __shared__ float qs[2*EPB];
    if (threadIdx.x < 2*EPB)
        qs[threadIdx.x] = g_qsum[(b0 + threadIdx.x/EPB)*DD + e0 + (threadIdx.x % EPB)];
    __syncthreads();
    float a0 = 0.f, a1 = 0.f;
#pragma unroll
    for (int e = 0; e < EPB; e++) {
        float wk = Wk[(size_t)(e0 + e)*DD + d];
        a0 = fmaf(wk, qs[e],       a0);
        a1 = fmaf(wk, qs[EPB + e], a1);
    }
    int z = blockIdx.z;
    g_wp[(z*BB + b0+0)*DD + d] = a0;
    g_wp[(z*BB + b0+1)*DD + d] = a1;
}

// ---------------- K4: warp-autonomous, 2 rows/iter, packed f32x2 (R14, 38.3us @68% DRAM) ----
__global__ void __launch_bounds__(TPB) k_attn(const float* __restrict__ cr) {
    int b = blockIdx.y, ch = blockIdx.x;
    int tid = threadIdx.x, warp = tid >> 5, lane = tid & 31;

    __shared__ float s_ws[DD];
    __shared__ float s_acc[WPB][DD];
    __shared__ float s_m[WPB], s_l[WPB];
    __shared__ float s_f[WPB];

    // ws = sum of e-split partials (L2-resident)
    for (int i = tid; i < DD; i += TPB) {
        float a = 0.f;
#pragma unroll
        for (int z = 0; z < ESPL; z++) a += g_wp[(z*BB + b)*DD + i];
        s_ws[i] = a;
    }
    __syncthreads();

    // w into packed registers: 12 u64 pairs covering float4 slots lane+32*i
    u64 w[12];
    const float4* ws4 = reinterpret_cast<const float4*>(s_ws);
#pragma unroll
    for (int i = 0; i < 6; i++) {
        F4U t; t.f = ws4[lane + 32*i];
        w[2*i]   = t.u[0];
        w[2*i+1] = t.u[1];
    }

    const float4* rbase = reinterpret_cast<const float4*>(cr) +
                          ((size_t)b*LK + (size_t)ch*RPB + (size_t)warp*RPW)*D4 + lane;

    float m = -CUDART_INF_F, l = 0.f;
    u64 acc[12];
#pragma unroll
    for (int j = 0; j < 12; j++) acc[j] = 0ull;   // (0.0f, 0.0f)

    for (int r = 0; r < RPW; r += 2) {
        F4U v0[6], v1[6];
        const float4* row0 = rbase + (size_t)r*D4;
        const float4* row1 = row0 + D4;
#pragma unroll
        for (int i = 0; i < 6; i++) v0[i].f = row0[32*i];
#pragma unroll
        for (int i = 0; i < 6; i++) v1[i].f = row1[32*i];

        // packed dot products (24 FFMA2 instead of 48 FFMA)
        u64 s0p = 0ull, s1p = 0ull;
#pragma unroll
        for (int i = 0; i < 6; i++) {
            s0p = fma2(v0[i].u[0], w[2*i],   s0p);
            s0p = fma2(v0[i].u[1], w[2*i+1], s0p);
            s1p = fma2(v1[i].u[0], w[2*i],   s1p);
            s1p = fma2(v1[i].u[1], w[2*i+1], s1p);
        }
        float s0 = hadd2(s0p);
        float s1 = hadd2(s1p);
#pragma unroll
        for (int o = 16; o; o >>= 1) {
            s0 += __shfl_xor_sync(0xffffffffu, s0, o);
            s1 += __shfl_xor_sync(0xffffffffu, s1, o);
        }

        float mnew = fmaxf(m, fmaxf(s0, s1));
        float p0 = __expf(s0 - mnew);
        float p1 = __expf(s1 - mnew);
        if (mnew != m) {                       // warp-uniform branch
            float scale = __expf(m - mnew);    // 0 on first pair (m=-inf)
            l *= scale;
            u64 sc2 = pack2(scale, scale);
#pragma unroll
            for (int j = 0; j < 12; j++) acc[j] = mul2(acc[j], sc2);
            m = mnew;
        }
        l += p0 + p1;

        u64 p0p = pack2(p0, p0);
        u64 p1p = pack2(p1, p1);
#pragma unroll
        for (int i = 0; i < 6; i++) {
            acc[2*i]   = fma2(p0p, v0[i].u[0], acc[2*i]);
            acc[2*i+1] = fma2(p0p, v0[i].u[1], acc[2*i+1]);
            acc[2*i]   = fma2(p1p, v1[i].u[0], acc[2*i]);
            acc[2*i+1] = fma2(p1p, v1[i].u[1], acc[2*i+1]);
        }
    }

    // per-warp results to smem (same float4-slot layout -> natural dim order)
    if (lane == 0) { s_m[warp] = m; s_l[warp] = l; }
    float4* sa = reinterpret_cast<float4*>(s_acc[warp]);
#pragma unroll
    for (int i = 0; i < 6; i++) {
        F4U t; t.u[0] = acc[2*i]; t.u[1] = acc[2*i+1];
        sa[lane + 32*i] = t.f;
    }
    __syncthreads();

    // block combine -> chunk partial
    if (tid == 0) {
        float M = -CUDART_INF_F;
#pragma unroll
        for (int ww = 0; ww < WPB; ww++) M = fmaxf(M, s_m[ww]);
        float L = 0.f;
#pragma unroll
        for (int ww = 0; ww < WPB; ww++) {
            float f = __expf(s_m[ww] - M);
            s_f[ww] = f;
            L += s_l[ww] * f;
        }
        int cidx = b*NCH + ch;
        g_pm[cidx] = M; g_pl[cidx] = L;
    }
    __syncthreads();
    if (tid < D4) {
        float4 a = make_float4(0.f,0.f,0.f,0.f);
#pragma unroll
        for (int ww = 0; ww < WPB; ww++) {
            float f = s_f[ww];
            float4 v = reinterpret_cast<const float4*>(s_acc[ww])[tid];
            a.x = fmaf(f, v.x, a.x); a.y = fmaf(f, v.y, a.y);
            a.z = fmaf(f, v.z, a.z); a.w = fmaf(f, v.w, a.w);
        }
        reinterpret_cast<float4*>(g_pacc)[(b*NCH + ch)*D4 + tid] = a;
    }
}

// ---------------- K5a: combine chunk partials -> v_in[b,d] ----------------
__global__ void k_comb() {
    int b = blockIdx.x, tid = threadIdx.x;   // 192 threads
    __shared__ float f[NCH];
    __shared__ float invL;
    if (tid == 0) {
        float M = -CUDART_INF_F;
        for (int c = 0; c < NCH; c++) M = fmaxf(M, g_pm[b*NCH + c]);
        float L = 0.f;
        for (int c = 0; c < NCH; c++) {
            float fc = __expf(g_pm[b*NCH + c] - M);
            f[c] = fc;
            L += g_pl[b*NCH + c] * fc;
        }
        invL = 1.0f / L;
    }
    __syncthreads();
    float4 v = make_float4(0.f, 0.f, 0.f, 0.f);
#pragma unroll
    for (int c = 0; c < NCH; c++) {
        float fc = f[c];
        float4 a = reinterpret_cast<const float4*>(g_pacc)[(b*NCH + c)*D4 + tid];
        v.x = fmaf(a.x, fc, v.x); v.y = fmaf(a.y, fc, v.y);
        v.z = fmaf(a.z, fc, v.z); v.w = fmaf(a.w, fc, v.w);
    }
    v.x *= invL; v.y *= invL; v.z *= invL; v.w *= invL;
    reinterpret_cast<float4*>(g_vin)[b*D4 + tid] = v;
}

// ---------------- K5b: out[b,e] — 8 interleaved dot products per warp ----------------
// Same structure as k_qsum (the verified 13.4->~4us fix), over g_vin instead of g_ssum.
__global__ void k_out(const float* __restrict__ Wv, const float* __restrict__ bv,
                      float* __restrict__ out) {
    int e = blockIdx.x;
    __shared__ float wrow[DD];
    for (int i = threadIdx.x; i < D4; i += 128)
        reinterpret_cast<float4*>(wrow)[i] =
            reinterpret_cast<const float4*>(Wv + (size_t)e*DD)[i];
    __syncthreads();
    int warp = threadIdx.x >> 5, lane = threadIdx.x & 31;
    int b0 = warp * 8;

    float4 w[6];
    const float4* w4 = reinterpret_cast<const float4*>(wrow);
#pragma unroll
    for (int i = 0; i < 6; i++) w[i] = w4[lane + 32*i];

    const float4* v4 = reinterpret_cast<const float4*>(g_vin);
    float acc[8];
#pragma unroll
    for (int j = 0; j < 8; j++) acc[j] = 0.f;

#pragma unroll
    for (int i = 0; i < 6; i++) {
#pragma unroll
        for (int j = 0; j < 8; j++) {
            float4 v = v4[(size_t)(b0 + j)*D4 + lane + 32*i];
            acc[j] = fmaf(w[i].x, v.x, acc[j]);
            acc[j] = fmaf(w[i].y, v.y, acc[j]);
            acc[j] = fmaf(w[i].z, v.z, acc[j]);
            acc[j] = fmaf(w[i].w, v.w, acc[j]);
        }
    }
#pragma unroll
    for (int o = 16; o; o >>= 1) {
#pragma unroll
        for (int j = 0; j < 8; j++)
            acc[j] += __shfl_xor_sync(0xffffffffu, acc[j], o);
    }
    if (lane == 0) {
        float bve = bv[e];
#pragma unroll
        for (int j = 0; j < 8; j++)
            out[(b0 + j)*DD + e] = acc[j] + bve;
    }
}

extern "C" void kernel_launch(void* const* d_in, const int* in_sizes, int n_in,
                              void* d_out, int out_size) {
    const float* sr = (const float*)d_in[0];   // sentence_rep [32,512,768]
    const float* cr = (const float*)d_in[1];   // comment_rep  [32,2048,768]
    const float* Wq = (const float*)d_in[2];
    const float* bq = (const float*)d_in[3];
    const float* Wk = (const float*)d_in[4];
    // d_in[5] = bk — exactly cancels in softmax, unused
    const float* Wv = (const float*)d_in[6];
    const float* bv = (const float*)d_in[7];
    float* out = (float*)d_out;

    k_ssum<<<dim3(NQC, BB), D4>>>(sr);
    k_qsum<<<DD, 128>>>(Wq, bq);
    k_w<<<dim3(DD/128, BB/2, ESPL), 128>>>(Wk);
    k_attn<<<dim3(NCH, BB), TPB>>>(cr);
    k_comb<<<BB, D4>>>();
    k_out<<<DD, 128>>>(Wv, bv, out);
}

// round 17
// speedup vs baseline: 1.2270x; 1.0071x over previous
#include <cuda_runtime.h>
#include <cstdint>
#include <math_constants.h>

#define BB   32
#define LQ   512
#define LK   2048
#define DD   768
#define D4   (DD/4)     // 192
#define NQC  16
#define QPC  (LQ/NQC)   // 32
#define RPW  32         // rows (keys) per warp
#define WPB  8          // warps per block
#define RPB  (RPW*WPB)  // 256 rows per block
#define NCH  (LK/RPB)   // 8 chunks per batch
#define TPB  256
#define ESPL 16
#define EPB  (DD/ESPL)  // 48

typedef unsigned long long u64;

// packed f32x2 helpers (SASS FFMA2/FMUL2 — only reachable via explicit PTX)
__device__ __forceinline__ u64 pack2(float x, float y) {
    u64 r; asm("mov.b64 %0, {%1, %2};" : "=l"(r) : "f"(x), "f"(y)); return r;
}
__device__ __forceinline__ u64 fma2(u64 a, u64 b, u64 c) {
    u64 d; asm("fma.rn.f32x2 %0, %1, %2, %3;" : "=l"(d) : "l"(a), "l"(b), "l"(c)); return d;
}
__device__ __forceinline__ u64 mul2(u64 a, u64 b) {
    u64 d; asm("mul.rn.f32x2 %0, %1, %2;" : "=l"(d) : "l"(a), "l"(b)); return d;
}
__device__ __forceinline__ float hadd2(u64 v) {
    float x, y; asm("mov.b64 {%0, %1}, %2;" : "=f"(x), "=f"(y) : "l"(v)); return x + y;
}

union F4U { float4 f; u64 u[2]; };

// scratch (device globals — no allocation allowed)
__device__ float g_sp  [BB*NQC*DD];
__device__ float g_ssum[BB*DD];
__device__ float g_qsum[BB*DD];
__device__ float g_wp  [ESPL*BB*DD];
__device__ float g_pm  [BB*NCH];
__device__ float g_pl  [BB*NCH];
__device__ float g_pacc[BB*NCH*DD];
__device__ float g_vin [BB*DD];
__device__ int   g_cnt [BB];    // zero-init; self-resets each use

// ---------------- K1: row-sums of sentence_rep, fused partial+reduce (R14, verified) ----
__global__ void k_ssum(const float* __restrict__ sr) {
    int qc = blockIdx.x, b = blockIdx.y, t = threadIdx.x;   // t < 192
    const float4* p = reinterpret_cast<const float4*>(sr) +
                      ((size_t)b*LQ + (size_t)qc*QPC)*D4 + t;
    float4 a = make_float4(0.f,0.f,0.f,0.f);
#pragma unroll
    for (int q = 0; q < QPC; q++) {
        float4 v = p[(size_t)q*D4];
        a.x += v.x; a.y += v.y; a.z += v.z; a.w += v.w;
    }
    reinterpret_cast<float4*>(g_sp)[(b*NQC + qc)*D4 + t] = a;

    __threadfence();
    __syncthreads();
    __shared__ int s_last;
    if (t == 0) s_last = (atomicAdd(&g_cnt[b], 1) == NQC-1);
    __syncthreads();
    if (s_last) {
        if (t == 0) g_cnt[b] = 0;   // reset for next graph replay
        float4 r = make_float4(0.f,0.f,0.f,0.f);
#pragma unroll
        for (int c = 0; c < NQC; c++) {
            float4 v = reinterpret_cast<const float4*>(g_sp)[(b*NQC + c)*D4 + t];
            r.x += v.x; r.y += v.y; r.z += v.z; r.w += v.w;
        }
        reinterpret_cast<float4*>(g_ssum)[b*D4 + t] = r;
    }
}

// ---------------- K2: q_sum[b,e] — 8 interleaved dot products per warp (R9, verified) ----
__global__ void k_qsum(const float* __restrict__ Wq, const float* __restrict__ bq) {
    int e = blockIdx.x;
    __shared__ float wrow[DD];
    for (int i = threadIdx.x; i < D4; i += 128)
        reinterpret_cast<float4*>(wrow)[i] =
            reinterpret_cast<const float4*>(Wq + (size_t)e*DD)[i];
    __syncthreads();
    int warp = threadIdx.x >> 5, lane = threadIdx.x & 31;
    int b0 = warp * 8;

    float4 w[6];
    const float4* w4 = reinterpret_cast<const float4*>(wrow);
#pragma unroll
    for (int i = 0; i < 6; i++) w[i] = w4[lane + 32*i];

    const float4* s4 = reinterpret_cast<const float4*>(g_ssum);
    float acc[8];
#pragma unroll
    for (int j = 0; j < 8; j++) acc[j] = 0.f;

#pragma unroll
    for (int i = 0; i < 6; i++) {
#pragma unroll
        for (int j = 0; j < 8; j++) {
            float4 s = s4[(size_t)(b0 + j)*D4 + lane + 32*i];
            acc[j] = fmaf(w[i].x, s.x, acc[j]);
            acc[j] = fmaf(w[i].y, s.y, acc[j]);
            acc[j] = fmaf(w[i].z, s.z, acc[j]);
            acc[j] = fmaf(w[i].w, s.w, acc[j]);
        }
    }
#pragma unroll
    for (int o = 16; o; o >>= 1) {
#pragma unroll
        for (int j = 0; j < 8; j++)
            acc[j] += __shfl_xor_sync(0xffffffffu, acc[j], o);
    }
    if (lane == 0) {
        float be = 512.0f * bq[e];
#pragma unroll
        for (int j = 0; j < 8; j++)
            g_qsum[(b0 + j)*DD + e] = acc[j] + be;
    }
}

// ---------------- K3: w partials — R3 shape, full unroll (R14, verified) ----------------
__global__ void k_w(const float* __restrict__ Wk) {
    int d  = blockIdx.x * 128 + threadIdx.x;
    int b0 = blockIdx.y * 2;
    int e0 = blockIdx.z * EPB;
    __shared__ float qs[2*EPB];
    if (threadIdx.x < 2*EPB)
        qs[threadIdx.x] = g_qsum[(b0 + threadIdx.x/EPB)*DD + e0 + (threadIdx.x % EPB)];
    __syncthreads();
    float a0 = 0.f, a1 = 0.f;
#pragma unroll
    for (int e = 0; e < EPB; e++) {
        float wk = Wk[(size_t)(e0 + e)*DD + d];
        a0 = fmaf(wk, qs[e],       a0);
        a1 = fmaf(wk, qs[EPB + e], a1);
    }
    int z = blockIdx.z;
    g_wp[(z*BB + b0+0)*DD + d] = a0;
    g_wp[(z*BB + b0+1)*DD + d] = a1;
}

// ---------------- K4: warp-autonomous, 2 rows/iter, packed f32x2 (R14, 38.3us @68% DRAM) ----
__global__ void __launch_bounds__(TPB) k_attn(const float* __restrict__ cr) {
    int b = blockIdx.y, ch = blockIdx.x;
    int tid = threadIdx.x, warp = tid >> 5, lane = tid & 31;

    __shared__ float s_ws[DD];
    __shared__ float s_acc[WPB][DD];
    __shared__ float s_m[WPB], s_l[WPB];
    __shared__ float s_f[WPB];

    // ws = sum of e-split partials (L2-resident)
    for (int i = tid; i < DD; i += TPB) {
        float a = 0.f;
#pragma unroll
        for (int z = 0; z < ESPL; z++) a += g_wp[(z*BB + b)*DD + i];
        s_ws[i] = a;
    }
    __syncthreads();

    // w into packed registers: 12 u64 pairs covering float4 slots lane+32*i
    u64 w[12];
    const float4* ws4 = reinterpret_cast<const float4*>(s_ws);
#pragma unroll
    for (int i = 0; i < 6; i++) {
        F4U t; t.f = ws4[lane + 32*i];
        w[2*i]   = t.u[0];
        w[2*i+1] = t.u[1];
    }

    const float4* rbase = reinterpret_cast<const float4*>(cr) +
                          ((size_t)b*LK + (size_t)ch*RPB + (size_t)warp*RPW)*D4 + lane;

    float m = -CUDART_INF_F, l = 0.f;
    u64 acc[12];
#pragma unroll
    for (int j = 0; j < 12; j++) acc[j] = 0ull;   // (0.0f, 0.0f)

    for (int r = 0; r < RPW; r += 2) {
        F4U v0[6], v1[6];
        const float4* row0 = rbase + (size_t)r*D4;
        const float4* row1 = row0 + D4;
#pragma unroll
        for (int i = 0; i < 6; i++) v0[i].f = row0[32*i];
#pragma unroll
        for (int i = 0; i < 6; i++) v1[i].f = row1[32*i];

        // packed dot products (24 FFMA2 instead of 48 FFMA)
        u64 s0p = 0ull, s1p = 0ull;
#pragma unroll
        for (int i = 0; i < 6; i++) {
            s0p = fma2(v0[i].u[0], w[2*i],   s0p);
            s0p = fma2(v0[i].u[1], w[2*i+1], s0p);
            s1p = fma2(v1[i].u[0], w[2*i],   s1p);
            s1p = fma2(v1[i].u[1], w[2*i+1], s1p);
        }
        float s0 = hadd2(s0p);
        float s1 = hadd2(s1p);
#pragma unroll
        for (int o = 16; o; o >>= 1) {
            s0 += __shfl_xor_sync(0xffffffffu, s0, o);
            s1 += __shfl_xor_sync(0xffffffffu, s1, o);
        }

        float mnew = fmaxf(m, fmaxf(s0, s1));
        float p0 = __expf(s0 - mnew);
        float p1 = __expf(s1 - mnew);
        if (mnew != m) {                       // warp-uniform branch
            float scale = __expf(m - mnew);    // 0 on first pair (m=-inf)
            l *= scale;
            u64 sc2 = pack2(scale, scale);
#pragma unroll
            for (int j = 0; j < 12; j++) acc[j] = mul2(acc[j], sc2);
            m = mnew;
        }
        l += p0 + p1;

        u64 p0p = pack2(p0, p0);
        u64 p1p = pack2(p1, p1);
#pragma unroll
        for (int i = 0; i < 6; i++) {
            acc[2*i]   = fma2(p0p, v0[i].u[0], acc[2*i]);
            acc[2*i+1] = fma2(p0p, v0[i].u[1], acc[2*i+1]);
            acc[2*i]   = fma2(p1p, v1[i].u[0], acc[2*i]);
            acc[2*i+1] = fma2(p1p, v1[i].u[1], acc[2*i+1]);
        }
    }

    // per-warp results to smem (same float4-slot layout -> natural dim order)
    if (lane == 0) { s_m[warp] = m; s_l[warp] = l; }
    float4* sa = reinterpret_cast<float4*>(s_acc[warp]);
#pragma unroll
    for (int i = 0; i < 6; i++) {
        F4U t; t.u[0] = acc[2*i]; t.u[1] = acc[2*i+1];
        sa[lane + 32*i] = t.f;
    }
    __syncthreads();

    // block combine -> chunk partial
    if (tid == 0) {
        float M = -CUDART_INF_F;
#pragma unroll
        for (int ww = 0; ww < WPB; ww++) M = fmaxf(M, s_m[ww]);
        float L = 0.f;
#pragma unroll
        for (int ww = 0; ww < WPB; ww++) {
            float f = __expf(s_m[ww] - M);
            s_f[ww] = f;
            L += s_l[ww] * f;
        }
        int cidx = b*NCH + ch;
        g_pm[cidx] = M; g_pl[cidx] = L;
    }
    __syncthreads();
    if (tid < D4) {
        float4 a = make_float4(0.f,0.f,0.f,0.f);
#pragma unroll
        for (int ww = 0; ww < WPB; ww++) {
            float f = s_f[ww];
            float4 v = reinterpret_cast<const float4*>(s_acc[ww])[tid];
            a.x = fmaf(f, v.x, a.x); a.y = fmaf(f, v.y, a.y);
            a.z = fmaf(f, v.z, a.z); a.w = fmaf(f, v.w, a.w);
        }
        reinterpret_cast<float4*>(g_pacc)[(b*NCH + ch)*D4 + tid] = a;
    }
}

// ---------------- K5a: combine chunk partials -> v_in[b,d] ----------------
__global__ void k_comb() {
    int b = blockIdx.x, tid = threadIdx.x;   // 192 threads
    __shared__ float f[NCH];
    __shared__ float invL;
    if (tid == 0) {
        float M = -CUDART_INF_F;
        for (int c = 0; c < NCH; c++) M = fmaxf(M, g_pm[b*NCH + c]);
        float L = 0.f;
        for (int c = 0; c < NCH; c++) {
            float fc = __expf(g_pm[b*NCH + c] - M);
            f[c] = fc;
            L += g_pl[b*NCH + c] * fc;
        }
        invL = 1.0f / L;
    }
    __syncthreads();
    float4 v = make_float4(0.f, 0.f, 0.f, 0.f);
#pragma unroll
    for (int c = 0; c < NCH; c++) {
        float fc = f[c];
        float4 a = reinterpret_cast<const float4*>(g_pacc)[(b*NCH + c)*D4 + tid];
        v.x = fmaf(a.x, fc, v.x); v.y = fmaf(a.y, fc, v.y);
        v.z = fmaf(a.z, fc, v.z); v.w = fmaf(a.w, fc, v.w);
    }
    v.x *= invL; v.y *= invL; v.z *= invL; v.w *= invL;
    reinterpret_cast<float4*>(g_vin)[b*D4 + tid] = v;
}

// ---------------- K5b: out[b,e] — 8 interleaved dot products per warp ----------------
// Same structure as k_qsum (the verified 13.4->~4us fix), over g_vin instead of g_ssum.
__global__ void k_out(const float* __restrict__ Wv, const float* __restrict__ bv,
                      float* __restrict__ out) {
    int e = blockIdx.x;
    __shared__ float wrow[DD];
    for (int i = threadIdx.x; i < D4; i += 128)
        reinterpret_cast<float4*>(wrow)[i] =
            reinterpret_cast<const float4*>(Wv + (size_t)e*DD)[i];
    __syncthreads();
    int warp = threadIdx.x >> 5, lane = threadIdx.x & 31;
    int b0 = warp * 8;

    float4 w[6];
    const float4* w4 = reinterpret_cast<const float4*>(wrow);
#pragma unroll
    for (int i = 0; i < 6; i++) w[i] = w4[lane + 32*i];

    const float4* v4 = reinterpret_cast<const float4*>(g_vin);
    float acc[8];
#pragma unroll
    for (int j = 0; j < 8; j++) acc[j] = 0.f;

#pragma unroll
    for (int i = 0; i < 6; i++) {
#pragma unroll
        for (int j = 0; j < 8; j++) {
            float4 v = v4[(size_t)(b0 + j)*D4 + lane + 32*i];
            acc[j] = fmaf(w[i].x, v.x, acc[j]);
            acc[j] = fmaf(w[i].y, v.y, acc[j]);
            acc[j] = fmaf(w[i].z, v.z, acc[j]);
            acc[j] = fmaf(w[i].w, v.w, acc[j]);
        }
    }
#pragma unroll
    for (int o = 16; o; o >>= 1) {
#pragma unroll
        for (int j = 0; j < 8; j++)
            acc[j] += __shfl_xor_sync(0xffffffffu, acc[j], o);
    }
    if (lane == 0) {
        float bve = bv[e];
#pragma unroll
        for (int j = 0; j < 8; j++)
            out[(b0 + j)*DD + e] = acc[j] + bve;
    }
}

extern "C" void kernel_launch(void* const* d_in, const int* in_sizes, int n_in,
                              void* d_out, int out_size) {
    const float* sr = (const float*)d_in[0];   // sentence_rep [32,512,768]
    const float* cr = (const float*)d_in[1];   // comment_rep  [32,2048,768]
    const float* Wq = (const float*)d_in[2];
    const float* bq = (const float*)d_in[3];
    const float* Wk = (const float*)d_in[4];
    // d_in[5] = bk — exactly cancels in softmax, unused
    const float* Wv = (const float*)d_in[6];
    const float* bv = (const float*)d_in[7];
    float* out = (float*)d_out;

    k_ssum<<<dim3(NQC, BB), D4>>>(sr);
    k_qsum<<<DD, 128>>>(Wq, bq);
    k_w<<<dim3(DD/128, BB/2, ESPL), 128>>>(Wk);
    k_attn<<<dim3(NCH, BB), TPB>>>(cr);
    k_comb<<<BB, D4>>>();
    k_out<<<DD, 128>>>(Wv, bv, out);
}